// round 1
// baseline (speedup 1.0000x reference)
#include <cuda_runtime.h>
#include <math.h>

#define B_   4
#define C_   256
#define CQ   32
#define HW   3136
#define TJ   32     // key tile
#define MQ   32     // queries per block

// ---------------- scratch (static device globals; no allocation) ----------------
__device__ float g_qT[B_ * HW * CQ];   // [B][N][Cq]
__device__ float g_kT[B_ * HW * CQ];   // [B][N][Cq]
__device__ float g_vT[B_ * HW * C_];   // [B][N][C]
__device__ float g_inv_norm;

// ==================== K1: fused QKV projection (320x256 GEMM) ====================
// out[m][b,n] = W[m,:] @ x[b,:,n] + bias[m];  rows 0..31 -> q, 32..63 -> k, 64..319 -> v
// grid (HW/64, 5, B), block 256. BM=64, BN=64, BK=32, thread tile 4x4.
#define BM 64
#define BN 64
#define BK 32

__global__ __launch_bounds__(256) void qkv_kernel(
    const float* __restrict__ x,
    const float* __restrict__ Wq, const float* __restrict__ bq,
    const float* __restrict__ Wk, const float* __restrict__ bk,
    const float* __restrict__ Wv, const float* __restrict__ bv)
{
    __shared__ float Ws[BM * 33];  // [m][kk] padded
    __shared__ float Xs[BK * 68];  // [kk][n] padded

    const int tid = threadIdx.x;
    const int n0  = blockIdx.x * BN;
    const int m0  = blockIdx.y * BM;
    const int b   = blockIdx.z;
    const int tm  = (tid / 16) * 4;
    const int tn  = (tid % 16) * 4;

    float acc[4][4];
#pragma unroll
    for (int r = 0; r < 4; r++)
#pragma unroll
        for (int c = 0; c < 4; c++) acc[r][c] = 0.f;

    for (int k0 = 0; k0 < C_; k0 += BK) {
        // load W tile (64 rows x 32 k)
#pragma unroll
        for (int p = 0; p < 2; p++) {
            int m  = tid / 8 + p * 32;
            int kk = (tid % 8) * 4;
            int mg = m0 + m;
            const float* wrow;
            if (mg < 32)       wrow = Wq + mg * C_;
            else if (mg < 64)  wrow = Wk + (mg - 32) * C_;
            else               wrow = Wv + (mg - 64) * C_;
            float4 w4 = *(const float4*)(wrow + k0 + kk);
            Ws[m * 33 + kk + 0] = w4.x;
            Ws[m * 33 + kk + 1] = w4.y;
            Ws[m * 33 + kk + 2] = w4.z;
            Ws[m * 33 + kk + 3] = w4.w;
        }
        // load X tile (32 k x 64 n)
#pragma unroll
        for (int p = 0; p < 2; p++) {
            int f  = tid + p * 256;
            int kk = f / 16;
            int c4 = (f % 16) * 4;
            float4 xv = *(const float4*)(x + ((size_t)b * C_ + k0 + kk) * HW + n0 + c4);
            *(float4*)(Xs + kk * 68 + c4) = xv;
        }
        __syncthreads();
#pragma unroll
        for (int kk = 0; kk < BK; kk++) {
            float a[4];
#pragma unroll
            for (int r = 0; r < 4; r++) a[r] = Ws[(tm + r) * 33 + kk];
            float4 b4 = *(float4*)(Xs + kk * 68 + tn);
#pragma unroll
            for (int r = 0; r < 4; r++) {
                acc[r][0] += a[r] * b4.x;
                acc[r][1] += a[r] * b4.y;
                acc[r][2] += a[r] * b4.z;
                acc[r][3] += a[r] * b4.w;
            }
        }
        __syncthreads();
    }

    // bias + store to transposed layouts. Thread's 4 m-rows stay in one region
    // (region boundaries 32/64 are multiples of 4; tm is a multiple of 4).
    int mg = m0 + tm;
    float* dst; int dim, mo; const float* bias;
    if (mg < 32)      { dst = g_qT; dim = CQ;  mo = mg;      bias = bq + mo; }
    else if (mg < 64) { dst = g_kT; dim = CQ;  mo = mg - 32; bias = bk + mo; }
    else              { dst = g_vT; dim = C_;  mo = mg - 64; bias = bv + mo; }
    float b0 = bias[0], b1 = bias[1], b2 = bias[2], b3 = bias[3];
#pragma unroll
    for (int c = 0; c < 4; c++) {
        int n = n0 + tn + c;
        float4 val;
        val.x = acc[0][c] + b0;
        val.y = acc[1][c] + b1;
        val.z = acc[2][c] + b2;
        val.w = acc[3][c] + b3;
        *(float4*)(dst + ((size_t)b * HW + n) * dim + mo) = val;
    }
}

// ==================== K2: Lipschitz norm scalar ====================
__global__ __launch_bounds__(256) void norm_kernel(
    const float* __restrict__ Wq, const float* __restrict__ Wk,
    const float* __restrict__ Wv)
{
    __shared__ float red[256];
    const int c = threadIdx.x;

    float u2p = 0.f;
    for (int i = c; i < CQ * C_; i += 256) { float w = Wq[i]; u2p += w * w; }

    float k2 = 0.f;
    for (int o = 0; o < CQ; o++) { float w = Wk[o * C_ + c]; k2 += w * w; }
    float v2 = 0.f;
    for (int o = 0; o < C_; o++) { float w = Wv[o * C_ + c]; v2 += w * w; }
    float colmax = fmaxf(k2, v2);

    red[c] = u2p; __syncthreads();
    for (int s = 128; s > 0; s >>= 1) {
        if (c < s) red[c] += red[c + s];
        __syncthreads();
    }
    float u2 = red[0];
    __syncthreads();
    red[c] = colmax; __syncthreads();
    for (int s = 128; s > 0; s >>= 1) {
        if (c < s) red[c] = fmaxf(red[c], red[c + s]);
        __syncthreads();
    }
    if (c == 0) {
        float norm = sqrtf(u2) * sqrtf(red[0]);  // u * max(vn, wn)
        g_inv_norm = 1.0f / norm;
    }
}

// ==================== K3: flash attention + epilogue ====================
// grid (HW/MQ = 98, B), block 128 (4 warps). Warp w owns queries 8w..8w+7,
// all 256 channels. Online softmax; epilogue: out = gamma*acc/(l*bound) + x.
__global__ __launch_bounds__(128, 3) void attn_kernel(
    const float* __restrict__ x,
    const float* __restrict__ gamma,
    float* __restrict__ out)
{
    __shared__ float sm[2304 + TJ * C_];  // 10496 floats = 41984 B
    float* k_s = sm;          // [32][36]
    float* p_s = sm + 1152;   // [32][36]  (p_s[j][qi])
    float* v_s = sm + 2304;   // [32][256]
    float* o_s = sm;          // epilogue reuse: [32][260] = 8320 floats

    const int tid  = threadIdx.x;
    const int lane = tid & 31;
    const int w    = tid >> 5;
    const int b    = blockIdx.y;
    const int i0   = blockIdx.x * MQ;
    const int iq   = lane >> 2;       // 0..7 query within warp
    const int qi   = w * 8 + iq;      // 0..31 query within block
    const int jl   = lane & 3;

    const float inv_norm = g_inv_norm;
    const size_t base = (size_t)b * HW;
    const float* kbase = g_kT + base * CQ;
    const float* vbase = g_vT + base * C_;

    // preload this lane's query row (32 floats), replicated across the quad
    float4 q4[8];
    const float4* qp = (const float4*)(g_qT + (base + i0 + qi) * CQ);
#pragma unroll
    for (int t = 0; t < 8; t++) q4[t] = qp[t];

    float acc[8][8];
#pragma unroll
    for (int i = 0; i < 8; i++)
#pragma unroll
        for (int r = 0; r < 8; r++) acc[i][r] = 0.f;
    float m_run = -1e30f, l_run = 0.f;

    const int cA = lane * 4;
    const int cB = 128 + lane * 4;

    for (int j0 = 0; j0 < HW; j0 += TJ) {
        __syncthreads();   // previous tile fully consumed
        // load K tile: 32x32 floats
#pragma unroll
        for (int p = 0; p < 2; p++) {
            int f  = tid + p * 128;
            int j  = f >> 3;
            int c4 = (f & 7) << 2;
            *(float4*)(k_s + j * 36 + c4) =
                *(const float4*)(kbase + (size_t)(j0 + j) * CQ + c4);
        }
        // load V tile: 32x256 floats
#pragma unroll
        for (int p = 0; p < 16; p++) {
            int f  = tid + p * 128;
            int j  = f >> 6;
            int c4 = (f & 63) << 2;
            *(float4*)(v_s + j * 256 + c4) =
                *(const float4*)(vbase + (size_t)(j0 + j) * C_ + c4);
        }
        __syncthreads();

        // ---- scores: this lane computes s[t] = q . k_{jl+4t} ----
        float s[8];
#pragma unroll
        for (int t = 0; t < 8; t++) {
            const float* kr = k_s + (jl + 4 * t) * 36;
            float s0 = 0.f, s1 = 0.f, s2 = 0.f, s3 = 0.f;
#pragma unroll
            for (int c = 0; c < 8; c++) {
                float4 kv = *(const float4*)(kr + 4 * c);
                s0 += q4[c].x * kv.x; s1 += q4[c].y * kv.y;
                s2 += q4[c].z * kv.z; s3 += q4[c].w * kv.w;
            }
            s[t] = ((s0 + s1) + (s2 + s3)) * inv_norm;
        }
        // ---- online softmax over the 4-lane quad owning this query ----
        float mt = s[0];
#pragma unroll
        for (int t = 1; t < 8; t++) mt = fmaxf(mt, s[t]);
        mt = fmaxf(mt, __shfl_xor_sync(0xffffffffu, mt, 1));
        mt = fmaxf(mt, __shfl_xor_sync(0xffffffffu, mt, 2));
        float m_new = fmaxf(m_run, mt);
        float alpha = __expf(m_run - m_new);
        m_run = m_new;
        float ls = 0.f;
#pragma unroll
        for (int t = 0; t < 8; t++) {
            float p = __expf(s[t] - m_new);
            ls += p;
            p_s[(jl + 4 * t) * 36 + qi] = p;
        }
        ls += __shfl_xor_sync(0xffffffffu, ls, 1);
        ls += __shfl_xor_sync(0xffffffffu, ls, 2);
        l_run = l_run * alpha + ls;
        __syncwarp();  // p_s is warp-private: only warp-level visibility needed

        // rescale accumulators by each query's alpha
        float al[8];
#pragma unroll
        for (int i = 0; i < 8; i++) al[i] = __shfl_sync(0xffffffffu, alpha, i * 4);
#pragma unroll
        for (int i = 0; i < 8; i++)
#pragma unroll
            for (int r = 0; r < 8; r++) acc[i][r] *= al[i];

        // ---- AV: 64 FMA per thread per j, 4 LDS.128 per warp per j ----
#pragma unroll 4
        for (int j = 0; j < TJ; j++) {
            float4 pa = *(const float4*)(p_s + j * 36 + w * 8);
            float4 pb = *(const float4*)(p_s + j * 36 + w * 8 + 4);
            float4 va = *(const float4*)(v_s + j * 256 + cA);
            float4 vb = *(const float4*)(v_s + j * 256 + cB);
            float pv[8] = {pa.x, pa.y, pa.z, pa.w, pb.x, pb.y, pb.z, pb.w};
            float vv[8] = {va.x, va.y, va.z, va.w, vb.x, vb.y, vb.z, vb.w};
#pragma unroll
            for (int i = 0; i < 8; i++)
#pragma unroll
                for (int r = 0; r < 8; r++) acc[i][r] += pv[i] * vv[r];
        }
    }
    __syncthreads();

    // ---- epilogue: scale, transpose through smem, add residual, store ----
    float l_arr[8];
#pragma unroll
    for (int i = 0; i < 8; i++) l_arr[i] = __shfl_sync(0xffffffffu, l_run, i * 4);
    const float g = gamma[0];
    const double bound_d = exp(sqrt(3.0)) * sqrt((double)HW / (double)C_) + 2.0 * sqrt(6.0);
    const float invb = (float)(1.0 / bound_d);

#pragma unroll
    for (int i = 0; i < 8; i++) {
        float sc = g * invb / l_arr[i];
        int q = w * 8 + i;
        float4 oa, ob;
        oa.x = acc[i][0] * sc; oa.y = acc[i][1] * sc;
        oa.z = acc[i][2] * sc; oa.w = acc[i][3] * sc;
        ob.x = acc[i][4] * sc; ob.y = acc[i][5] * sc;
        ob.z = acc[i][6] * sc; ob.w = acc[i][7] * sc;
        *(float4*)(o_s + q * 260 + cA) = oa;
        *(float4*)(o_s + q * 260 + cB) = ob;
    }
    __syncthreads();

#pragma unroll
    for (int p = 0; p < 2; p++) {
        int c = tid + p * 128;
        const float* xr = x + ((size_t)b * C_ + c) * HW + i0;
        float* orow = out + ((size_t)b * C_ + c) * HW + i0;
#pragma unroll
        for (int u = 0; u < 8; u++) {
            float4 xv = *(const float4*)(xr + u * 4);
            float4 ov;
            ov.x = o_s[(u * 4 + 0) * 260 + c] + xv.x;
            ov.y = o_s[(u * 4 + 1) * 260 + c] + xv.y;
            ov.z = o_s[(u * 4 + 2) * 260 + c] + xv.z;
            ov.w = o_s[(u * 4 + 3) * 260 + c] + xv.w;
            *(float4*)(orow + u * 4) = ov;
        }
    }
}

// ==================== launch ====================
extern "C" void kernel_launch(void* const* d_in, const int* in_sizes, int n_in,
                              void* d_out, int out_size)
{
    const float* x     = (const float*)d_in[0];
    const float* Wq    = (const float*)d_in[1];
    const float* bq    = (const float*)d_in[2];
    const float* Wk    = (const float*)d_in[3];
    const float* bk    = (const float*)d_in[4];
    const float* Wv    = (const float*)d_in[5];
    const float* bv    = (const float*)d_in[6];
    const float* gamma = (const float*)d_in[7];
    float* out = (float*)d_out;

    dim3 g1(HW / BN, (CQ + CQ + C_) / BM, B_);  // (49, 5, 4)
    qkv_kernel<<<g1, 256>>>(x, Wq, bq, Wk, bk, Wv, bv);

    norm_kernel<<<1, 256>>>(Wq, Wk, Wv);

    dim3 g3(HW / MQ, B_);                        // (98, 4)
    attn_kernel<<<g3, 128>>>(x, gamma, out);
}

// round 5
// speedup vs baseline: 2.7908x; 2.7908x over previous
#include <cuda_runtime.h>
#include <cuda_bf16.h>
#include <math.h>
#include <stdint.h>

#define B_   4
#define C_   256
#define CQ   32
#define NTOK 3136
#define TJ   32     // keys per tile
#define MQ   64     // queries per block

// ---------------- scratch (static device globals) ----------------
__device__ __nv_bfloat16 g_qb[B_ * NTOK * CQ];   // [B][N][Cq], pre-scaled by inv_norm
__device__ __nv_bfloat16 g_kb[B_ * NTOK * CQ];   // [B][N][Cq]
__device__ __nv_bfloat16 g_vb[B_ * C_ * NTOK];   // [B][C][N]
__device__ float g_inv_norm;

// ==================== K2: Lipschitz norm scalar (runs FIRST) ====================
__global__ __launch_bounds__(256) void norm_kernel(
    const float* __restrict__ Wq, const float* __restrict__ Wk,
    const float* __restrict__ Wv)
{
    __shared__ float red[256];
    const int c = threadIdx.x;

    float u2p = 0.f;
    for (int i = c; i < CQ * C_; i += 256) { float w = Wq[i]; u2p += w * w; }

    float k2 = 0.f;
    for (int o = 0; o < CQ; o++) { float w = Wk[o * C_ + c]; k2 += w * w; }
    float v2 = 0.f;
    for (int o = 0; o < C_; o++) { float w = Wv[o * C_ + c]; v2 += w * w; }
    float colmax = fmaxf(k2, v2);

    red[c] = u2p; __syncthreads();
    for (int s = 128; s > 0; s >>= 1) {
        if (c < s) red[c] += red[c + s];
        __syncthreads();
    }
    float u2 = red[0];
    __syncthreads();
    red[c] = colmax; __syncthreads();
    for (int s = 128; s > 0; s >>= 1) {
        if (c < s) red[c] = fmaxf(red[c], red[c + s]);
        __syncthreads();
    }
    if (c == 0) g_inv_norm = 1.0f / (sqrtf(u2) * sqrtf(red[0]));
}

// ==================== K1: fused QKV projection -> bf16 ====================
#define BM 64
#define BN 64
#define BK 32

__global__ __launch_bounds__(256) void qkv_kernel(
    const float* __restrict__ x,
    const float* __restrict__ Wq, const float* __restrict__ bq,
    const float* __restrict__ Wk, const float* __restrict__ bk,
    const float* __restrict__ Wv, const float* __restrict__ bv)
{
    __shared__ float Ws[BM * 33];
    __shared__ float Xs[BK * 68];

    const int tid = threadIdx.x;
    const int n0  = blockIdx.x * BN;
    const int m0  = blockIdx.y * BM;
    const int b   = blockIdx.z;
    const int tm  = (tid / 16) * 4;
    const int tn  = (tid % 16) * 4;

    float acc[4][4];
#pragma unroll
    for (int r = 0; r < 4; r++)
#pragma unroll
        for (int c = 0; c < 4; c++) acc[r][c] = 0.f;

    for (int k0 = 0; k0 < C_; k0 += BK) {
#pragma unroll
        for (int p = 0; p < 2; p++) {
            int m  = tid / 8 + p * 32;
            int kk = (tid % 8) * 4;
            int mg = m0 + m;
            const float* wrow;
            if (mg < 32)       wrow = Wq + mg * C_;
            else if (mg < 64)  wrow = Wk + (mg - 32) * C_;
            else               wrow = Wv + (mg - 64) * C_;
            float4 w4 = *(const float4*)(wrow + k0 + kk);
            Ws[m * 33 + kk + 0] = w4.x;
            Ws[m * 33 + kk + 1] = w4.y;
            Ws[m * 33 + kk + 2] = w4.z;
            Ws[m * 33 + kk + 3] = w4.w;
        }
#pragma unroll
        for (int p = 0; p < 2; p++) {
            int f  = tid + p * 256;
            int kk = f / 16;
            int c4 = (f % 16) * 4;
            float4 xv = *(const float4*)(x + ((size_t)b * C_ + k0 + kk) * NTOK + n0 + c4);
            *(float4*)(Xs + kk * 68 + c4) = xv;
        }
        __syncthreads();
#pragma unroll
        for (int kk = 0; kk < BK; kk++) {
            float a[4];
#pragma unroll
            for (int r = 0; r < 4; r++) a[r] = Ws[(tm + r) * 33 + kk];
            float4 b4 = *(float4*)(Xs + kk * 68 + tn);
#pragma unroll
            for (int r = 0; r < 4; r++) {
                acc[r][0] += a[r] * b4.x;
                acc[r][1] += a[r] * b4.y;
                acc[r][2] += a[r] * b4.z;
                acc[r][3] += a[r] * b4.w;
            }
        }
        __syncthreads();
    }

    int mg = m0 + tm;
    if (mg < 64) {
        // q or k: transposed layout [N][32] bf16
        bool isq = (mg < 32);
        __nv_bfloat16* dst = isq ? g_qb : g_kb;
        int mo = mg & 31;
        const float* bias = isq ? (bq + mo) : (bk + mo);
        float scale = isq ? g_inv_norm : 1.0f;
        float b0 = bias[0], b1 = bias[1], b2 = bias[2], b3 = bias[3];
#pragma unroll
        for (int c = 0; c < 4; c++) {
            int n = n0 + tn + c;
            float v0 = (acc[0][c] + b0) * scale;
            float v1 = (acc[1][c] + b1) * scale;
            float v2 = (acc[2][c] + b2) * scale;
            float v3 = (acc[3][c] + b3) * scale;
            __nv_bfloat162* p = (__nv_bfloat162*)(dst + ((size_t)b * NTOK + n) * CQ + mo);
            p[0] = __floats2bfloat162_rn(v0, v1);
            p[1] = __floats2bfloat162_rn(v2, v3);
        }
    } else {
        // v: natural layout [C][N] bf16
        int c0 = mg - 64;
#pragma unroll
        for (int r = 0; r < 4; r++) {
            float bb = bv[c0 + r];
            __nv_bfloat162* p = (__nv_bfloat162*)(g_vb + ((size_t)b * C_ + c0 + r) * NTOK + n0 + tn);
            p[0] = __floats2bfloat162_rn(acc[r][0] + bb, acc[r][1] + bb);
            p[1] = __floats2bfloat162_rn(acc[r][2] + bb, acc[r][3] + bb);
        }
    }
}

// ==================== K3: bf16 mma flash attention ====================
__device__ __forceinline__ void ldsm4(uint32_t& r0, uint32_t& r1, uint32_t& r2,
                                      uint32_t& r3, uint32_t a) {
    asm volatile("ldmatrix.sync.aligned.m8n8.x4.shared.b16 {%0,%1,%2,%3}, [%4];\n"
                 : "=r"(r0), "=r"(r1), "=r"(r2), "=r"(r3) : "r"(a));
}
__device__ __forceinline__ void mma16816(float c[4], uint32_t a0, uint32_t a1,
                                         uint32_t a2, uint32_t a3,
                                         uint32_t b0, uint32_t b1) {
    asm volatile(
        "mma.sync.aligned.m16n8k16.row.col.f32.bf16.bf16.f32 "
        "{%0,%1,%2,%3},{%4,%5,%6,%7},{%8,%9},{%0,%1,%2,%3};\n"
        : "+f"(c[0]), "+f"(c[1]), "+f"(c[2]), "+f"(c[3])
        : "r"(a0), "r"(a1), "r"(a2), "r"(a3), "r"(b0), "r"(b1));
}
__device__ __forceinline__ uint32_t packbf(float lo, float hi) {
    __nv_bfloat162 h = __floats2bfloat162_rn(lo, hi);
    return *reinterpret_cast<uint32_t*>(&h);
}
#define CPA(dst, src) asm volatile("cp.async.cg.shared.global [%0], [%1], 16;\n" :: "r"(dst), "l"(src))
#define CPC() asm volatile("cp.async.commit_group;\n" ::: "memory")
#define CPW(n) asm volatile("cp.async.wait_group %0;\n" :: "n"(n) : "memory")

// smem layout (bytes): Q[64][40]bf16 @0 (5120), K bufs [32][40] @5120 (2x2560),
// V bufs [256][40] @10240 (2x20480). Total 51200. Epilogue stage fp32 @10240.
#define SMEM_K   5120
#define SMEM_V   10240
#define SMEM_TOT 51200

__global__ __launch_bounds__(256, 2) void attn_bf16(
    const float* __restrict__ x,
    const float* __restrict__ gamma,
    float* __restrict__ out)
{
    extern __shared__ char smem_raw[];
    const int tid  = threadIdx.x;
    const int lane = tid & 31;
    const int w    = tid >> 5;
    const int b    = blockIdx.y;
    const int i0   = blockIdx.x * MQ;
    const int qg   = w >> 1;      // query group (16 rows)
    const int ch   = w & 1;       // channel half
    const int g    = lane >> 3;   // ldmatrix lane group
    const int L    = lane & 7;
    const int tig  = lane & 3;
    const int grp  = lane >> 2;

    uint32_t sbase = (uint32_t)__cvta_generic_to_shared(smem_raw);
    uint32_t q_s  = sbase;
    uint32_t k_s0 = sbase + SMEM_K;
    uint32_t v_s0 = sbase + SMEM_V;

    // --- issue Q load (own group) ---
    {
        int row = tid >> 2, cc = tid & 3;
        const __nv_bfloat16* src = g_qb + ((size_t)b * NTOK + i0 + row) * CQ + cc * 8;
        CPA(q_s + (uint32_t)(row * 80 + cc * 16), src);
    }
    CPC();

    // --- tile issue helper ---
    auto issue_tile = [&](int t) {
        int buf = t & 1;
        int j0  = t * TJ;
        if (tid < 128) {
            int row = tid >> 2, cc = tid & 3;
            const __nv_bfloat16* src = g_kb + ((size_t)b * NTOK + j0 + row) * CQ + cc * 8;
            CPA(k_s0 + buf * 2560 + (uint32_t)(row * 80 + cc * 16), src);
        }
#pragma unroll
        for (int i = 0; i < 4; i++) {
            int row = (tid >> 2) + i * 64, cc = tid & 3;
            const __nv_bfloat16* src = g_vb + ((size_t)b * C_ + row) * NTOK + j0 + cc * 8;
            CPA(v_s0 + buf * 20480 + (uint32_t)(row * 80 + cc * 16), src);
        }
        CPC();
    };
    issue_tile(0);

    CPW(1);                 // Q arrived (tile0 may still be in flight)
    __syncthreads();

    // --- Q fragments (held in regs for whole kernel) ---
    uint32_t qf[2][4];
#pragma unroll
    for (int kc = 0; kc < 2; kc++) {
        uint32_t addr = q_s + (uint32_t)(((qg * 16 + (g & 1) * 8 + L) * 40
                                          + (g >> 1) * 8 + kc * 16) * 2);
        ldsm4(qf[kc][0], qf[kc][1], qf[kc][2], qf[kc][3], addr);
    }

    // lane-relative byte offsets for B-operand ldmatrix
    const uint32_t kloff = (uint32_t)((((g >> 1) * 8 + L) * 40 + (g & 1) * 8) * 2);
    const uint32_t vloff = (uint32_t)(((ch * 128 + (g >> 1) * 8 + L) * 40 + (g & 1) * 8) * 2);

    float acc[16][4];
#pragma unroll
    for (int i = 0; i < 16; i++)
#pragma unroll
        for (int r = 0; r < 4; r++) acc[i][r] = 0.f;
    float m0 = -1e30f, m1 = -1e30f, l0 = 0.f, l1 = 0.f;

    const int NT = NTOK / TJ;  // 98
    for (int t = 0; t < NT; t++) {
        CPW(0);            // tile t landed
        __syncthreads();
        if (t + 1 < NT) issue_tile(t + 1);

        uint32_t kb_ = k_s0 + (t & 1) * 2560;
        uint32_t vb_ = v_s0 + (t & 1) * 20480;

        // ---- S = Q K^T ----
        float S[4][4];
#pragma unroll
        for (int nt = 0; nt < 4; nt++)
#pragma unroll
            for (int r = 0; r < 4; r++) S[nt][r] = 0.f;
#pragma unroll
        for (int kc = 0; kc < 2; kc++)
#pragma unroll
            for (int jt2 = 0; jt2 < 2; jt2++) {
                uint32_t r0, r1, r2, r3;
                ldsm4(r0, r1, r2, r3, kb_ + kloff + (uint32_t)(jt2 * 1280 + kc * 32));
                mma16816(S[2 * jt2],     qf[kc][0], qf[kc][1], qf[kc][2], qf[kc][3], r0, r1);
                mma16816(S[2 * jt2 + 1], qf[kc][0], qf[kc][1], qf[kc][2], qf[kc][3], r2, r3);
            }

        // ---- online softmax (rows grp, grp+8) ----
        float mx0 = fmaxf(fmaxf(S[0][0], S[0][1]), fmaxf(S[1][0], S[1][1]));
        mx0 = fmaxf(mx0, fmaxf(fmaxf(S[2][0], S[2][1]), fmaxf(S[3][0], S[3][1])));
        float mx1 = fmaxf(fmaxf(S[0][2], S[0][3]), fmaxf(S[1][2], S[1][3]));
        mx1 = fmaxf(mx1, fmaxf(fmaxf(S[2][2], S[2][3]), fmaxf(S[3][2], S[3][3])));
        mx0 = fmaxf(mx0, __shfl_xor_sync(0xffffffffu, mx0, 1));
        mx0 = fmaxf(mx0, __shfl_xor_sync(0xffffffffu, mx0, 2));
        mx1 = fmaxf(mx1, __shfl_xor_sync(0xffffffffu, mx1, 1));
        mx1 = fmaxf(mx1, __shfl_xor_sync(0xffffffffu, mx1, 2));
        float mn0 = fmaxf(m0, mx0), mn1 = fmaxf(m1, mx1);
        float a0 = __expf(m0 - mn0), a1 = __expf(m1 - mn1);
        m0 = mn0; m1 = mn1;
        float s0 = 0.f, s1 = 0.f;
#pragma unroll
        for (int nt = 0; nt < 4; nt++) {
            S[nt][0] = __expf(S[nt][0] - mn0); s0 += S[nt][0];
            S[nt][1] = __expf(S[nt][1] - mn0); s0 += S[nt][1];
            S[nt][2] = __expf(S[nt][2] - mn1); s1 += S[nt][2];
            S[nt][3] = __expf(S[nt][3] - mn1); s1 += S[nt][3];
        }
        s0 += __shfl_xor_sync(0xffffffffu, s0, 1);
        s0 += __shfl_xor_sync(0xffffffffu, s0, 2);
        s1 += __shfl_xor_sync(0xffffffffu, s1, 1);
        s1 += __shfl_xor_sync(0xffffffffu, s1, 2);
        l0 = l0 * a0 + s0;
        l1 = l1 * a1 + s1;
#pragma unroll
        for (int cn = 0; cn < 16; cn++) {
            acc[cn][0] *= a0; acc[cn][1] *= a0;
            acc[cn][2] *= a1; acc[cn][3] *= a1;
        }

        // ---- acc += P V ----
#pragma unroll
        for (int jt = 0; jt < 2; jt++) {
            uint32_t p0 = packbf(S[2 * jt][0],     S[2 * jt][1]);
            uint32_t p1 = packbf(S[2 * jt][2],     S[2 * jt][3]);
            uint32_t p2 = packbf(S[2 * jt + 1][0], S[2 * jt + 1][1]);
            uint32_t p3 = packbf(S[2 * jt + 1][2], S[2 * jt + 1][3]);
#pragma unroll
            for (int cnp = 0; cnp < 8; cnp++) {
                uint32_t r0, r1, r2, r3;
                ldsm4(r0, r1, r2, r3, vb_ + vloff + (uint32_t)(cnp * 1280 + jt * 32));
                mma16816(acc[2 * cnp],     p0, p1, p2, p3, r0, r1);
                mma16816(acc[2 * cnp + 1], p0, p1, p2, p3, r2, r3);
            }
        }
        __syncthreads();
    }

    // ==================== epilogue ====================
    const double bound_d = exp(sqrt(3.0)) * sqrt((double)NTOK / (double)C_) + 2.0 * sqrt(6.0);
    const float gs = gamma[0] * (float)(1.0 / bound_d);
    const float sc0 = gs / l0, sc1 = gs / l1;
    float* stage = (float*)(smem_raw + SMEM_V);
    const int r0 = qg * 16 + grp, r1 = r0 + 8;
    const int cb = tig * 2;

#pragma unroll
    for (int ph = 0; ph < 2; ph++) {
        if (ch == ph) {
#pragma unroll
            for (int cn = 0; cn < 16; cn++) {
                int cl = cn * 8 + cb;
                stage[r0 * 132 + cl]     = acc[cn][0] * sc0;
                stage[r0 * 132 + cl + 1] = acc[cn][1] * sc0;
                stage[r1 * 132 + cl]     = acc[cn][2] * sc1;
                stage[r1 * 132 + cl + 1] = acc[cn][3] * sc1;
            }
        }
        __syncthreads();
        int c  = tid >> 1;
        int q0 = (tid & 1) * 32;
        const float* xr   = x   + ((size_t)b * C_ + ph * 128 + c) * NTOK + i0 + q0;
        float*       orow = out + ((size_t)b * C_ + ph * 128 + c) * NTOK + i0 + q0;
#pragma unroll
        for (int u = 0; u < 8; u++) {
            float4 xv = *(const float4*)(xr + u * 4);
            float4 ov;
            ov.x = stage[(q0 + u * 4 + 0) * 132 + c] + xv.x;
            ov.y = stage[(q0 + u * 4 + 1) * 132 + c] + xv.y;
            ov.z = stage[(q0 + u * 4 + 2) * 132 + c] + xv.z;
            ov.w = stage[(q0 + u * 4 + 3) * 132 + c] + xv.w;
            *(float4*)(orow + u * 4) = ov;
        }
        __syncthreads();
    }
}

// ==================== launch ====================
extern "C" void kernel_launch(void* const* d_in, const int* in_sizes, int n_in,
                              void* d_out, int out_size)
{
    const float* x     = (const float*)d_in[0];
    const float* Wq    = (const float*)d_in[1];
    const float* bq    = (const float*)d_in[2];
    const float* Wk    = (const float*)d_in[3];
    const float* bk    = (const float*)d_in[4];
    const float* Wv    = (const float*)d_in[5];
    const float* bv    = (const float*)d_in[6];
    const float* gamma = (const float*)d_in[7];
    float* out = (float*)d_out;

    cudaFuncSetAttribute(attn_bf16, cudaFuncAttributeMaxDynamicSharedMemorySize, SMEM_TOT);

    norm_kernel<<<1, 256>>>(Wq, Wk, Wv);

    dim3 g1(NTOK / BN, (CQ + CQ + C_) / BM, B_);  // (49, 5, 4)
    qkv_kernel<<<g1, 256>>>(x, Wq, bq, Wk, bk, Wv, bv);

    dim3 g3(NTOK / MQ, B_);                        // (49, 4)
    attn_bf16<<<g3, 256, SMEM_TOT>>>(x, gamma, out);
}